// round 8
// baseline (speedup 1.0000x reference)
#include <cuda_runtime.h>
#include <cuda_bf16.h>
#include <cstdint>

// Indexer gather: out[i, :] = items[min(floor(clamp(indices[i],0,1)*1024), 1023), :]
// indices: [1048576] f32, items: [1024, 256] f32, out: [1048576, 256] f32.
//
// R5: persistent grid-stride version of R4. Exactly one full-occupancy wave
// (148 SM x 8 CTA = 1184 CTAs, 256 thr) loops over the R4 layout: each
// thread-slot owns 4 float4 chunks of one output row (cols (slot&15)+16i),
// one L1-broadcast index load -> 4 independent L2-hit gathers -> 4 streaming
// stores. Removes ~54 wave transitions + per-CTA setup, self-balances the
// late-CTA L1tex-queue straggler tail, and lets consecutive loop iterations
// overlap (loads of iter k+1 behind stores of iter k).

static constexpr int N_INDICES   = 1048576;
static constexpr int D_ITEM      = 256;
static constexpr int N_ITEMS     = 1024;
static constexpr int VEC_PER_ROW = D_ITEM / 4;     // 64
static constexpr int ITERS       = 4;              // float4 chunks per thread-slot
static constexpr int THREADS     = 256;
static constexpr unsigned TOTAL_SLOTS = (unsigned)(N_INDICES * (VEC_PER_ROW / ITERS)); // 2^24
static constexpr int NUM_SMS     = 148;
static constexpr int CTAS_PER_SM = 8;
static constexpr int BLOCKS      = NUM_SMS * CTAS_PER_SM;   // 1184

__global__ __launch_bounds__(THREADS, CTAS_PER_SM)
void indexer_gather_kernel(const float* __restrict__ indices,
                           const float4* __restrict__ items,
                           float4* __restrict__ out)
{
    const unsigned span = (unsigned)BLOCKS * THREADS;            // 303104
    unsigned slot = blockIdx.x * blockDim.x + threadIdx.x;

    for (; slot < TOTAL_SLOTS; slot += span) {
        unsigned row = slot >> 4;        // output/index row (< 2^20)
        unsigned c0  = slot & 15u;       // base float4 column

        float x = __ldg(&indices[row]);  // broadcast within 16-lane group
        x = fminf(fmaxf(x, 0.0f), 1.0f) * (float)N_ITEMS;
        int closest = min((int)floorf(x), N_ITEMS - 1);
        const float4* irow = items + (unsigned)closest * VEC_PER_ROW;

        float4 val[ITERS];
        #pragma unroll
        for (int i = 0; i < ITERS; i++) {
            val[i] = __ldg(&irow[c0 + 16u * i]);       // 4 independent L2-hit gathers
        }

        float4* orow = out + (unsigned long long)row * VEC_PER_ROW;
        #pragma unroll
        for (int i = 0; i < ITERS; i++) {
            __stcs(&orow[c0 + 16u * i], val[i]);       // streaming stores, coalesced
        }
    }
}

extern "C" void kernel_launch(void* const* d_in, const int* in_sizes, int n_in,
                              void* d_out, int out_size)
{
    const float*  indices = (const float*)d_in[0];
    const float4* items   = (const float4*)d_in[1];
    float4*       out     = (float4*)d_out;

    indexer_gather_kernel<<<BLOCKS, THREADS>>>(indices, items, out);
}

// round 11
// speedup vs baseline: 1.1522x; 1.1522x over previous
#include <cuda_runtime.h>
#include <cuda_bf16.h>
#include <cstdint>

// Indexer gather: out[i, :] = items[min(floor(clamp(indices[i],0,1)*1024), 1023), :]
// indices: [1048576] f32, items: [1024, 256] f32, out: [1048576, 256] f32.
//
// R6: R4 layout, two rows per thread in a straight line. Each thread owns
// slots s and s+2^23 (two different output rows, same 4-column pattern).
// BOTH index loads issue at the top, so row 1's ~240-cycle index-load
// latency is hidden behind row 0's gathers+stores. val[4] registers are
// reused across the two halves -> regs stay ~32, occupancy 8 preserved
// (avoids R3's 48-reg collapse). 32768 independent straight-line CTAs
// (no grid-stride loop -- R5 showed the loop serializes the stream).

static constexpr int N_INDICES   = 1048576;
static constexpr int D_ITEM      = 256;
static constexpr int N_ITEMS     = 1024;
static constexpr int VEC_PER_ROW = D_ITEM / 4;     // 64
static constexpr int ITERS       = 4;              // float4 chunks per row-slot
static constexpr int THREADS     = 256;
static constexpr unsigned TOTAL_SLOTS = (unsigned)(N_INDICES * (VEC_PER_ROW / ITERS)); // 2^24
static constexpr unsigned HALF_SLOTS  = TOTAL_SLOTS / 2;                               // 2^23

__global__ __launch_bounds__(THREADS, 8)
void indexer_gather_kernel(const float* __restrict__ indices,
                           const float4* __restrict__ items,
                           float4* __restrict__ out)
{
    unsigned slot0 = blockIdx.x * blockDim.x + threadIdx.x;   // < 2^23
    unsigned slot1 = slot0 + HALF_SLOTS;

    unsigned row0 = slot0 >> 4;
    unsigned row1 = slot1 >> 4;
    unsigned c0   = slot0 & 15u;      // same low bits for both slots

    // Front-issue both index loads: row1's latency hides behind row0's work.
    float x0 = __ldg(&indices[row0]);
    float x1 = __ldg(&indices[row1]);

    // ---- row 0 ----
    {
        float x = fminf(fmaxf(x0, 0.0f), 1.0f) * (float)N_ITEMS;
        int closest = min((int)floorf(x), N_ITEMS - 1);
        const float4* irow = items + (unsigned)closest * VEC_PER_ROW;

        float4 val[ITERS];
        #pragma unroll
        for (int i = 0; i < ITERS; i++)
            val[i] = __ldg(&irow[c0 + 16u * i]);

        float4* orow = out + (unsigned long long)row0 * VEC_PER_ROW;
        #pragma unroll
        for (int i = 0; i < ITERS; i++)
            __stcs(&orow[c0 + 16u * i], val[i]);
    }

    // ---- row 1 ----
    {
        float x = fminf(fmaxf(x1, 0.0f), 1.0f) * (float)N_ITEMS;
        int closest = min((int)floorf(x), N_ITEMS - 1);
        const float4* irow = items + (unsigned)closest * VEC_PER_ROW;

        float4 val[ITERS];
        #pragma unroll
        for (int i = 0; i < ITERS; i++)
            val[i] = __ldg(&irow[c0 + 16u * i]);

        float4* orow = out + (unsigned long long)row1 * VEC_PER_ROW;
        #pragma unroll
        for (int i = 0; i < ITERS; i++)
            __stcs(&orow[c0 + 16u * i], val[i]);
    }
}

extern "C" void kernel_launch(void* const* d_in, const int* in_sizes, int n_in,
                              void* d_out, int out_size)
{
    const float*  indices = (const float*)d_in[0];
    const float4* items   = (const float4*)d_in[1];
    float4*       out     = (float4*)d_out;

    const unsigned blocks = HALF_SLOTS / THREADS;   // 32768
    indexer_gather_kernel<<<blocks, THREADS>>>(indices, items, out);
}